// round 13
// baseline (speedup 1.0000x reference)
#include <cuda_runtime.h>
#include <cuda_fp16.h>
#include <cstdint>

#define B_ 4
#define T_ 4096
#define HS_ 64
#define BM 128
#define KN 64
#define KC 1024
#define NCMAX 4

// Device scratch (no cudaMalloc allowed). 16B-aligned for vector/cp.async access.
__device__ __align__(16) __half g_qh[B_*T_*HS_], g_ql[B_*T_*HS_];
__device__ __align__(16) __half g_kh[B_*T_*HS_], g_kl[B_*T_*HS_];
__device__ __align__(16) __half g_vh[B_*HS_*T_];                    // V^T: [b][h][t] (hi only)
__device__ __align__(16) __half g_wh[192*64], g_wl[192*64];         // stacked [Wq;Wk;Wv]^T
__device__ float g_pm[B_*T_*NCMAX], g_pl[B_*T_*NCMAX];              // m in log2 units
__device__ __align__(16) __half g_po[(size_t)B_*T_*NCMAX*HS_];      // fp16 partials

// ---------------- PTX helpers (family-agnostic: sm_80+) ----------------
__device__ __forceinline__ uint32_t smem_u32(const void* p) {
    uint32_t a;
    asm("{ .reg .u64 t; cvta.to.shared.u64 t, %1; cvt.u32.u64 %0, t; }" : "=r"(a) : "l"(p));
    return a;
}
#define CP_ASYNC16(dst, src) \
    asm volatile("cp.async.cg.shared.global [%0], [%1], 16;" :: "r"(dst), "l"(src))
#define CP_COMMIT() asm volatile("cp.async.commit_group;" ::: "memory")
#define CP_WAIT(n)  asm volatile("cp.async.wait_group %0;" :: "n"(n) : "memory")

// D(16x8,f32) += A(16x16,f16) * B(16x8,f16)   row.col
#define MMA16816(D0,D1,D2,D3, A0,A1,A2,A3, B0,B1) \
    asm volatile("mma.sync.aligned.m16n8k16.row.col.f32.f16.f16.f32 " \
        "{%0,%1,%2,%3}, {%4,%5,%6,%7}, {%8,%9}, {%0,%1,%2,%3};" \
        : "+f"(D0), "+f"(D1), "+f"(D2), "+f"(D3) \
        : "r"(A0), "r"(A1), "r"(A2), "r"(A3), "r"(B0), "r"(B1))

#define LDSM4(R0,R1,R2,R3, ADDR) \
    asm volatile("ldmatrix.sync.aligned.m8n8.x4.shared.b16 {%0,%1,%2,%3}, [%4];" \
        : "=r"(R0), "=r"(R1), "=r"(R2), "=r"(R3) : "r"(ADDR))

__device__ __forceinline__ uint32_t h2u(__half2 h) { return *(uint32_t*)&h; }
__device__ __forceinline__ float ex2f(float x) {
    float r; asm("ex2.approx.f32 %0, %1;" : "=f"(r) : "f"(x)); return r;
}
__device__ __forceinline__ uint32_t ex2h2(uint32_t x) {
    uint32_t r; asm("ex2.approx.f16x2 %0, %1;" : "=r"(r) : "r"(x)); return r;
}
#define ONES16 0x3C003C00u   // half2(1.0, 1.0)

// Q scale: 8 (the reference's C**0.5) * log2(e) -> scores arrive in log2 units
#define QSCALE 11.5415603271117f

// ---------------- Kernel 0: W -> fp16 hi/lo, stacked [n=mat*64+h][k=d] ----------------
__global__ __launch_bounds__(256) void wconv_kernel(
    const float* __restrict__ Wq, const float* __restrict__ Wk, const float* __restrict__ Wv)
{
    const int id = blockIdx.x * 256 + threadIdx.x;    // 0..1535
    const int n = id >> 3, ch = id & 7;
    const int m = n >> 6, h = n & 63;
    const float* W = m == 0 ? Wq : (m == 1 ? Wk : Wv);
    float f[8];
#pragma unroll
    for (int dd = 0; dd < 8; dd++) f[dd] = W[(ch * 8 + dd) * 64 + h];
    uint4 hi, lo;
    uint32_t* hp = &hi.x;
    uint32_t* lp = &lo.x;
#pragma unroll
    for (int p = 0; p < 4; p++) {
        __half2 a = __floats2half2_rn(f[2*p], f[2*p+1]);
        hp[p] = h2u(a);
        __half2 bq = __floats2half2_rn(f[2*p]   - __half2float(__low2half(a)),
                                       f[2*p+1] - __half2float(__high2half(a)));
        lp[p] = h2u(bq);
    }
    *reinterpret_cast<uint4*>(&g_wh[n * 64 + ch * 8]) = hi;
    *reinterpret_cast<uint4*>(&g_wl[n * 64 + ch * 8]) = lo;
}

// ---------------- Kernel 1: tensor-core QKV projection ----------------
#define XA_H 0
#define XA_L 8192
#define WW_H 16384
#define WW_L 40960
#define PROJ_SMEM 65536

extern __shared__ char psm[];

__global__ __launch_bounds__(256, 2) void proj_kernel(const float* __restrict__ x)
{
    const int tid = threadIdx.x;
    const int wid = tid >> 5, lane = tid & 31;
    const int g = lane >> 2, tq = lane & 3;
    const int rows_base = blockIdx.x * 64;
    const uint32_t smb = smem_u32(psm);

    // ---- W tiles via cp.async (coalesced, L2-resident) ----
#pragma unroll
    for (int it = 0; it < 6; it++) {
        const int id = tid + it * 256;            // 0..1535
        const int n = id >> 3, ch = id & 7;
        const uint32_t off = n * 128 + ((ch ^ (n & 7)) << 4);
        CP_ASYNC16(smb + WW_H + off, g_wh + n * 64 + ch * 8);
        CP_ASYNC16(smb + WW_L + off, g_wl + n * 64 + ch * 8);
    }
    CP_COMMIT();

    // ---- x tile: fp32 -> fp16 hi/lo (through regs) ----
#pragma unroll
    for (int it = 0; it < 2; it++) {
        const int id = tid + it * 256;            // 0..511
        const int r = id >> 3, ch = id & 7;
        const float4* xp = reinterpret_cast<const float4*>(
            x + ((size_t)(rows_base + r)) * 64 + ch * 8);
        const float4 f0 = xp[0], f1 = xp[1];
        uint4 hi, lo;
        __half2 a, bq;
        a = __floats2half2_rn(f0.x, f0.y); hi.x = h2u(a);
        bq = __floats2half2_rn(f0.x - __half2float(__low2half(a)), f0.y - __half2float(__high2half(a))); lo.x = h2u(bq);
        a = __floats2half2_rn(f0.z, f0.w); hi.y = h2u(a);
        bq = __floats2half2_rn(f0.z - __half2float(__low2half(a)), f0.w - __half2float(__high2half(a))); lo.y = h2u(bq);
        a = __floats2half2_rn(f1.x, f1.y); hi.z = h2u(a);
        bq = __floats2half2_rn(f1.x - __half2float(__low2half(a)), f1.y - __half2float(__high2half(a))); lo.z = h2u(bq);
        a = __floats2half2_rn(f1.z, f1.w); hi.w = h2u(a);
        bq = __floats2half2_rn(f1.z - __half2float(__low2half(a)), f1.w - __half2float(__high2half(a))); lo.w = h2u(bq);
        const uint32_t off = r * 128 + ((ch ^ (r & 7)) << 4);
        *reinterpret_cast<uint4*>(psm + XA_H + off) = hi;
        *reinterpret_cast<uint4*>(psm + XA_L + off) = lo;
    }
    CP_WAIT(0);
    __syncthreads();

    const uint32_t* sAh = (const uint32_t*)(psm + XA_H);
    const uint32_t* sAl = (const uint32_t*)(psm + XA_L);
    const uint32_t* sWh = (const uint32_t*)(psm + WW_H);
    const uint32_t* sWl = (const uint32_t*)(psm + WW_L);

    uint32_t ah[16], al[16];
    {
        const int rb  = ((wid & 3) * 16 + g) * 32 + tq;
        const int rb8 = rb + 256;
#pragma unroll
        for (int kc = 0; kc < 4; kc++) {
            const int e0 = ((2 * kc) ^ g) << 2;
            const int e1 = ((2 * kc + 1) ^ g) << 2;
            ah[4*kc+0] = sAh[rb + e0];  ah[4*kc+1] = sAh[rb8 + e0];
            ah[4*kc+2] = sAh[rb + e1];  ah[4*kc+3] = sAh[rb8 + e1];
            al[4*kc+0] = sAl[rb + e0];  al[4*kc+1] = sAl[rb8 + e0];
            al[4*kc+2] = sAl[rb + e1];  al[4*kc+3] = sAl[rb8 + e1];
        }
    }

    const int nh = wid >> 2;                      // n-half: 0 or 1
    float D[12][4];
#pragma unroll
    for (int j = 0; j < 12; j++) { D[j][0]=0.f; D[j][1]=0.f; D[j][2]=0.f; D[j][3]=0.f; }

#pragma unroll
    for (int jj = 0; jj < 12; jj++) {
        const int jg = nh * 12 + jj;
        const int rbase = (8 * jg + g) * 32 + tq;
#pragma unroll
        for (int kc = 0; kc < 4; kc++) {
            const int e0 = ((2 * kc) ^ g) << 2;
            const int e1 = ((2 * kc + 1) ^ g) << 2;
            const uint32_t bh0 = sWh[rbase + e0], bh1 = sWh[rbase + e1];
            const uint32_t bl0 = sWl[rbase + e0], bl1 = sWl[rbase + e1];
            MMA16816(D[jj][0],D[jj][1],D[jj][2],D[jj][3], ah[4*kc],ah[4*kc+1],ah[4*kc+2],ah[4*kc+3], bh0,bh1);
            MMA16816(D[jj][0],D[jj][1],D[jj][2],D[jj][3], al[4*kc],al[4*kc+1],al[4*kc+2],al[4*kc+3], bh0,bh1);
            MMA16816(D[jj][0],D[jj][1],D[jj][2],D[jj][3], ah[4*kc],ah[4*kc+1],ah[4*kc+2],ah[4*kc+3], bl0,bl1);
        }
    }

    // ---- epilogue ----
    const int rg  = rows_base + (wid & 3) * 16 + g;
    const int rg8 = rg + 8;
    const int b = rg >> 12, t0 = rg & (T_ - 1), t8 = t0 + 8;

#pragma unroll
    for (int jj = 0; jj < 12; jj++) {
        const int j = nh * 12 + jj;
        const int h = 8 * (j & 7) + 2 * tq;
        float v0 = D[jj][0], v1 = D[jj][1], v2 = D[jj][2], v3 = D[jj][3];
        if (j < 8) { v0 *= QSCALE; v1 *= QSCALE; v2 *= QSCALE; v3 *= QSCALE; }  // Q * C**0.5 * log2(e)
        const __half2 hA = __floats2half2_rn(v0, v1);
        const __half2 hB = __floats2half2_rn(v2, v3);
        const __half2 lA = __floats2half2_rn(v0 - __half2float(__low2half(hA)),
                                             v1 - __half2float(__high2half(hA)));
        const __half2 lB = __floats2half2_rn(v2 - __half2float(__low2half(hB)),
                                             v3 - __half2float(__high2half(hB)));
        if (j < 8) {
            *(uint32_t*)&g_qh[(size_t)rg  * 64 + h] = h2u(hA);
            *(uint32_t*)&g_qh[(size_t)rg8 * 64 + h] = h2u(hB);
            *(uint32_t*)&g_ql[(size_t)rg  * 64 + h] = h2u(lA);
            *(uint32_t*)&g_ql[(size_t)rg8 * 64 + h] = h2u(lB);
        } else if (j < 16) {
            *(uint32_t*)&g_kh[(size_t)rg  * 64 + h] = h2u(hA);
            *(uint32_t*)&g_kh[(size_t)rg8 * 64 + h] = h2u(hB);
            *(uint32_t*)&g_kl[(size_t)rg  * 64 + h] = h2u(lA);
            *(uint32_t*)&g_kl[(size_t)rg8 * 64 + h] = h2u(lB);
        } else {
            const size_t r0 = ((size_t)b * 64 + h) * T_;
            const size_t r1 = ((size_t)b * 64 + h + 1) * T_;
            g_vh[r0 + t0] = __low2half(hA);  g_vh[r1 + t0] = __high2half(hA);
            g_vh[r0 + t8] = __low2half(hB);  g_vh[r1 + t8] = __high2half(hB);
        }
    }
}

// ---------------- Kernel 2: FA2-style mma.sync flash attention (split-K partials)
// SMEM: 2 x 24KB K/V double buffer (Kh,Kl,Vh) + 32KB Q (hi/lo) = 80KB/CTA, 2 CTAs/SM.
#define ABYTES 8192
#define BUFBYTES (3 * ABYTES)
#define QH_OFF 49152
#define QL_OFF 65536
#define SMEM_BYTES 81920

extern __shared__ char dsm[];

__device__ __forceinline__ void copy_tile(int b, int k0, int buf, int tid, uint32_t smb)
{
#pragma unroll
    for (int i = 0; i < 6; i++) {
        const int id = tid + i * 256;           // 0..1535
        const int arr = id >> 9;                // 0=Kh 1=Kl 2=Vh (uniform per i-range)
        const int r = (id >> 3) & 63;
        const int ch = id & 7;
        const uint32_t dst = smb + buf * BUFBYTES + arr * ABYTES + r * 128 + ((ch ^ (r & 7)) << 4);
        const __half* src;
        if (arr == 0)      src = g_kh + ((size_t)(b * T_ + k0 + r)) * 64 + ch * 8;
        else if (arr == 1) src = g_kl + ((size_t)(b * T_ + k0 + r)) * 64 + ch * 8;
        else               src = g_vh + ((size_t)(b * 64 + r)) * T_ + k0 + ch * 8;
        CP_ASYNC16(dst, src);
    }
}

__device__ __forceinline__ void copy_q(int b, int q0, int tid, uint32_t smb)
{
#pragma unroll
    for (int i = 0; i < 8; i++) {
        const int id = tid + i * 256;           // 0..2047
        const int arr = id >> 10;               // 0=qh, 1=ql
        const int r = (id >> 3) & 127;
        const int ch = id & 7;
        const uint32_t dst = smb + QH_OFF + arr * 16384 + r * 128 + ((ch ^ (r & 7)) << 4);
        const __half* src = (arr == 0 ? g_qh : g_ql) + ((size_t)(b * T_ + q0 + r)) * 64 + ch * 8;
        CP_ASYNC16(dst, src);
    }
}

__global__ __launch_bounds__(256, 2) void attn_kernel()
{
    const int b = blockIdx.y;
    // heavy-first (t, c) mapping: q-tile t has t/8+1 chunks; sum = 80
    int u = blockIdx.x, t = 0, c = 0;
#pragma unroll 1
    for (int tt = 31; tt >= 0; tt--) { int n = tt / 8 + 1; if (u < n) { t = tt; c = u; break; } u -= n; }
    const int q0 = t * BM, k0c = c * KC;
    const int kend = min(k0c + KC, (t + 1) * BM);
    const int nT = (kend - k0c) / KN;

    const int tid = threadIdx.x, wid = tid >> 5, lane = tid & 31;
    const int g = lane >> 2, tq = lane & 3;
    const int qi0 = q0 + wid * 16;
    const int rg = qi0 + g, rg8 = rg + 8;
    const uint32_t smb = smem_u32(dsm);

    // ldmatrix lane decomposition
    const int lr = lane & 7, q2 = lane >> 3;
    const uint32_t kv_row = (uint32_t)(((q2 >> 1) * 8 + lr) * 128);   // K/V: m-pair row offset
    const int eKV = q2 & 1;                                           // K/V: which k-chunk
    const uint32_t q_row = (uint32_t)((wid * 16 + (q2 & 1) * 8 + lr) * 128);  // Q rows
    const int eQ = q2 >> 1;

    float O[8][4];
#pragma unroll
    for (int j = 0; j < 8; j++) { O[j][0]=0.f; O[j][1]=0.f; O[j][2]=0.f; O[j][3]=0.f; }
    float Ol[4] = {0.f, 0.f, 0.f, 0.f};          // ones-column accumulator: l
    float m0 = -1e30f, m1 = -1e30f;

    copy_q(b, q0, tid, smb);
    copy_tile(b, k0c, 0, tid, smb);
    CP_COMMIT();
    CP_WAIT(0);
    __syncthreads();

    // ---- hoist Q-hi fragments (tile-invariant) into registers ----
    uint32_t qfh[16];
#pragma unroll
    for (int kc = 0; kc < 4; kc++) {
        const uint32_t chQ = (uint32_t)(((2 * kc + eQ) ^ lr) << 4);
        LDSM4(qfh[4*kc], qfh[4*kc+1], qfh[4*kc+2], qfh[4*kc+3], smb + QH_OFF + q_row + chQ);
    }

    for (int n = 0; n < nT; n++) {
        const int k0 = k0c + n * KN;
        const int buf = n & 1;
        // invariant at loop top: tile n resident + visible; all warps done with tile n-1
        if (n + 1 < nT) { copy_tile(b, k0 + KN, (n + 1) & 1, tid, smb); CP_COMMIT(); }

        const uint32_t kh_base = smb + buf * BUFBYTES + kv_row;
        const uint32_t vh_base = kh_base + 2 * ABYTES;

        // ---- S = Q·K^T (3-term hi/lo), Q-hi from regs; scores in log2 units ----
        float SD[8][4];
#pragma unroll
        for (int j = 0; j < 8; j++) { SD[j][0]=0.f; SD[j][1]=0.f; SD[j][2]=0.f; SD[j][3]=0.f; }
#pragma unroll
        for (int kc = 0; kc < 4; kc++) {
            const uint32_t chQ = (uint32_t)(((2 * kc + eQ) ^ lr) << 4);
            uint32_t c0r, c1r, c2r, c3r;
            LDSM4(c0r, c1r, c2r, c3r, smb + QL_OFF + q_row + chQ);
            const uint32_t a0 = qfh[4*kc], a1 = qfh[4*kc+1], a2 = qfh[4*kc+2], a3 = qfh[4*kc+3];
            const uint32_t chK = (uint32_t)(((2 * kc + eKV) ^ lr) << 4);
#pragma unroll
            for (int j0 = 0; j0 < 8; j0 += 2) {
                uint32_t bh0, bh1, bh2, bh3, bl0, bl1, bl2, bl3;
                LDSM4(bh0, bh1, bh2, bh3, kh_base + chK + j0 * 1024);
                LDSM4(bl0, bl1, bl2, bl3, kh_base + ABYTES + chK + j0 * 1024);
                MMA16816(SD[j0][0],SD[j0][1],SD[j0][2],SD[j0][3], a0,a1,a2,a3, bh0,bh1);
                MMA16816(SD[j0][0],SD[j0][1],SD[j0][2],SD[j0][3], c0r,c1r,c2r,c3r, bh0,bh1);
                MMA16816(SD[j0][0],SD[j0][1],SD[j0][2],SD[j0][3], a0,a1,a2,a3, bl0,bl1);
                MMA16816(SD[j0+1][0],SD[j0+1][1],SD[j0+1][2],SD[j0+1][3], a0,a1,a2,a3, bh2,bh3);
                MMA16816(SD[j0+1][0],SD[j0+1][1],SD[j0+1][2],SD[j0+1][3], c0r,c1r,c2r,c3r, bh2,bh3);
                MMA16816(SD[j0+1][0],SD[j0+1][1],SD[j0+1][2],SD[j0+1][3], a0,a1,a2,a3, bl2,bl3);
            }
        }

        // ---- causal mask (warp-uniform predicate) ----
        if (k0 + KN - 1 > qi0) {
#pragma unroll
            for (int j = 0; j < 8; j++) {
                const int col = k0 + 8 * j + 2 * tq;
                if (col     > rg)  SD[j][0] = -1e30f;
                if (col + 1 > rg)  SD[j][1] = -1e30f;
                if (col     > rg8) SD[j][2] = -1e30f;
                if (col + 1 > rg8) SD[j][3] = -1e30f;
            }
        }

        // ---- online softmax (log2 domain) ----
        float bm0 = -1e30f, bm1 = -1e30f;
#pragma unroll
        for (int j = 0; j < 8; j++) {
            bm0 = fmaxf(bm0, fmaxf(SD[j][0], SD[j][1]));
            bm1 = fmaxf(bm1, fmaxf(SD[j][2], SD[j][3]));
        }
        bm0 = fmaxf(bm0, __shfl_xor_sync(0xFFFFFFFFu, bm0, 1));
        bm0 = fmaxf(bm0, __shfl_xor_sync(0xFFFFFFFFu, bm0, 2));
        bm1 = fmaxf(bm1, __shfl_xor_sync(0xFFFFFFFFu, bm1, 1));
        bm1 = fmaxf(bm1, __shfl_xor_sync(0xFFFFFFFFu, bm1, 2));
        const float mn0 = fmaxf(m0, bm0), mn1 = fmaxf(m1, bm1);
        const float c0 = ex2f(m0 - mn0), c1 = ex2f(m1 - mn1);
        m0 = mn0; m1 = mn1;

#pragma unroll
        for (int j = 0; j < 8; j++) {
            O[j][0] *= c0; O[j][1] *= c0; O[j][2] *= c1; O[j][3] *= c1;
        }
        Ol[0] *= c0; Ol[1] *= c0; Ol[2] *= c1; Ol[3] *= c1;

        // ---- O += P·V  (p = ex2.f16x2(s - m); l via ones-column MMA; V hi only) ----
#pragma unroll
        for (int kc = 0; kc < 4; kc++) {
            const uint32_t pa0 = ex2h2(h2u(__floats2half2_rn(SD[2*kc][0]   - mn0, SD[2*kc][1]   - mn0)));
            const uint32_t pa1 = ex2h2(h2u(__floats2half2_rn(SD[2*kc][2]   - mn1, SD[2*kc][3]   - mn1)));
            const uint32_t pa2 = ex2h2(h2u(__floats2half2_rn(SD[2*kc+1][0] - mn0, SD[2*kc+1][1] - mn0)));
            const uint32_t pa3 = ex2h2(h2u(__floats2half2_rn(SD[2*kc+1][2] - mn1, SD[2*kc+1][3] - mn1)));
            MMA16816(Ol[0],Ol[1],Ol[2],Ol[3], pa0,pa1,pa2,pa3, ONES16,ONES16);
            const uint32_t chV = (uint32_t)(((2 * kc + eKV) ^ lr) << 4);
#pragma unroll
            for (int j0 = 0; j0 < 8; j0 += 2) {
                uint32_t vh0, vh1, vh2, vh3;
                LDSM4(vh0, vh1, vh2, vh3, vh_base + chV + j0 * 1024);
                MMA16816(O[j0][0],O[j0][1],O[j0][2],O[j0][3], pa0,pa1,pa2,pa3, vh0,vh1);
                MMA16816(O[j0+1][0],O[j0+1][1],O[j0+1][2],O[j0+1][3], pa0,pa1,pa2,pa3, vh2,vh3);
            }
        }

        // single barrier per tile: tile n+1 arrival + all-warps-done-tile-n
        if (n + 1 < nT) { CP_WAIT(0); }
        __syncthreads();
    }

    // ---- write partials (m log2; l from ones-column; O as fp16) ----
    const size_t p0 = ((size_t)(b * T_ + rg)) * NCMAX + c;
    const size_t p1 = ((size_t)(b * T_ + rg8)) * NCMAX + c;
    if (tq == 0) {
        g_pm[p0] = m0; g_pl[p0] = Ol[0];
        g_pm[p1] = m1; g_pl[p1] = Ol[2];
    }
#pragma unroll
    for (int j = 0; j < 8; j++) {
        *(uint32_t*)&g_po[p0 * 64 + 8 * j + 2 * tq] = h2u(__floats2half2_rn(O[j][0], O[j][1]));
        *(uint32_t*)&g_po[p1 * 64 + 8 * j + 2 * tq] = h2u(__floats2half2_rn(O[j][2], O[j][3]));
    }
}

// ---------------- Kernel 3: merge split-K partials (thread = (row, 8-col part), fp16 loads)
__global__ __launch_bounds__(256) void attn_reduce_kernel(float* __restrict__ out)
{
    const int gid2 = blockIdx.x * 256 + threadIdx.x;   // 0 .. B*T*8
    const int row = gid2 >> 3, part = gid2 & 7;
    const int qi = row & (T_ - 1);
    const int nc = (qi >> 7) / 8 + 1;
    const size_t pbase = (size_t)row * NCMAX;

    float mv[NCMAX];
#pragma unroll
    for (int cc = 0; cc < NCMAX; cc++) mv[cc] = (cc < nc) ? g_pm[pbase + cc] : -1e30f;
    float m = -1e30f;
#pragma unroll
    for (int cc = 0; cc < NCMAX; cc++) m = fmaxf(m, mv[cc]);

    float l = 0.f;
    float o[8];
#pragma unroll
    for (int i = 0; i < 8; i++) o[i] = 0.f;
#pragma unroll
    for (int cc = 0; cc < NCMAX; cc++) {
        if (cc < nc) {
            const float w = ex2f(mv[cc] - m);      // log2-domain partials
            l = fmaf(g_pl[pbase + cc], w, l);
            const uint4 v = *reinterpret_cast<const uint4*>(
                &g_po[(pbase + cc) * HS_ + part * 8]);
            const uint32_t* vp = &v.x;
#pragma unroll
            for (int p = 0; p < 4; p++) {
                const float2 f = __half22float2(*(const __half2*)&vp[p]);
                o[2*p]   = fmaf(w, f.x, o[2*p]);
                o[2*p+1] = fmaf(w, f.y, o[2*p+1]);
            }
        }
    }
    const float inv = 1.0f / l;
    float4 r0, r1;
    r0.x = o[0]*inv; r0.y = o[1]*inv; r0.z = o[2]*inv; r0.w = o[3]*inv;
    r1.x = o[4]*inv; r1.y = o[5]*inv; r1.z = o[6]*inv; r1.w = o[7]*inv;
    float4* op = reinterpret_cast<float4*>(&out[(size_t)row * HS_ + part * 8]);
    op[0] = r0; op[1] = r1;
}

// ---------------------------------------------------------------------------
extern "C" void kernel_launch(void* const* d_in, const int* in_sizes, int n_in,
                              void* d_out, int out_size)
{
    const float* x  = (const float*)d_in[0];
    const float* Wq = (const float*)d_in[1];
    const float* Wk = (const float*)d_in[2];
    const float* Wv = (const float*)d_in[3];
    float* out = (float*)d_out;

    cudaFuncSetAttribute(proj_kernel, cudaFuncAttributeMaxDynamicSharedMemorySize, PROJ_SMEM);
    cudaFuncSetAttribute(attn_kernel, cudaFuncAttributeMaxDynamicSharedMemorySize, SMEM_BYTES);

    wconv_kernel<<<6, 256>>>(Wq, Wk, Wv);
    proj_kernel<<<(B_ * T_) / 64, 256, PROJ_SMEM>>>(x);

    dim3 ag(80, B_);
    attn_kernel<<<ag, 256, SMEM_BYTES>>>();

    attn_reduce_kernel<<<(B_ * T_ * 8) / 256, 256>>>(out);
}

// round 14
// speedup vs baseline: 1.0216x; 1.0216x over previous
#include <cuda_runtime.h>
#include <cuda_fp16.h>
#include <cstdint>

#define B_ 4
#define T_ 4096
#define HS_ 64
#define BM 128
#define KN 64
#define KC 1024
#define NCMAX 4

// Device scratch (no cudaMalloc allowed). 16B-aligned for vector/cp.async access.
__device__ __align__(16) __half g_qh[B_*T_*HS_], g_ql[B_*T_*HS_];
__device__ __align__(16) __half g_kh[B_*T_*HS_], g_kl[B_*T_*HS_];
__device__ __align__(16) __half g_vh[B_*HS_*T_];                    // V^T: [b][h][t] (hi only)
__device__ __align__(16) __half g_wh[192*64], g_wl[192*64];         // stacked [Wq;Wk;Wv]^T
__device__ float g_pm[B_*T_*NCMAX], g_pl[B_*T_*NCMAX];              // m in log2 units
__device__ __align__(16) __half g_po[(size_t)B_*T_*NCMAX*HS_];      // fp16 partials

// ---------------- PTX helpers (family-agnostic: sm_80+) ----------------
__device__ __forceinline__ uint32_t smem_u32(const void* p) {
    uint32_t a;
    asm("{ .reg .u64 t; cvta.to.shared.u64 t, %1; cvt.u32.u64 %0, t; }" : "=r"(a) : "l"(p));
    return a;
}
#define CP_ASYNC16(dst, src) \
    asm volatile("cp.async.cg.shared.global [%0], [%1], 16;" :: "r"(dst), "l"(src))
#define CP_COMMIT() asm volatile("cp.async.commit_group;" ::: "memory")
#define CP_WAIT(n)  asm volatile("cp.async.wait_group %0;" :: "n"(n) : "memory")

// D(16x8,f32) += A(16x16,f16) * B(16x8,f16)   row.col
#define MMA16816(D0,D1,D2,D3, A0,A1,A2,A3, B0,B1) \
    asm volatile("mma.sync.aligned.m16n8k16.row.col.f32.f16.f16.f32 " \
        "{%0,%1,%2,%3}, {%4,%5,%6,%7}, {%8,%9}, {%0,%1,%2,%3};" \
        : "+f"(D0), "+f"(D1), "+f"(D2), "+f"(D3) \
        : "r"(A0), "r"(A1), "r"(A2), "r"(A3), "r"(B0), "r"(B1))

#define LDSM4(R0,R1,R2,R3, ADDR) \
    asm volatile("ldmatrix.sync.aligned.m8n8.x4.shared.b16 {%0,%1,%2,%3}, [%4];" \
        : "=r"(R0), "=r"(R1), "=r"(R2), "=r"(R3) : "r"(ADDR))

__device__ __forceinline__ uint32_t h2u(__half2 h) { return *(uint32_t*)&h; }
__device__ __forceinline__ float ex2f(float x) {
    float r; asm("ex2.approx.f32 %0, %1;" : "=f"(r) : "f"(x)); return r;
}
__device__ __forceinline__ uint32_t ex2h2(uint32_t x) {
    uint32_t r; asm("ex2.approx.f16x2 %0, %1;" : "=r"(r) : "r"(x)); return r;
}
#define ONES16 0x3C003C00u   // half2(1.0, 1.0)

// Q scale: 8 (the reference's C**0.5) * log2(e) -> scores arrive in log2 units
#define QSCALE 11.5415603271117f

// ---------------- Kernel 0: W -> fp16 hi/lo, stacked [n=mat*64+h][k=d] ----------------
__global__ __launch_bounds__(256) void wconv_kernel(
    const float* __restrict__ Wq, const float* __restrict__ Wk, const float* __restrict__ Wv)
{
    const int id = blockIdx.x * 256 + threadIdx.x;    // 0..1535
    const int n = id >> 3, ch = id & 7;
    const int m = n >> 6, h = n & 63;
    const float* W = m == 0 ? Wq : (m == 1 ? Wk : Wv);
    float f[8];
#pragma unroll
    for (int dd = 0; dd < 8; dd++) f[dd] = W[(ch * 8 + dd) * 64 + h];
    uint4 hi, lo;
    uint32_t* hp = &hi.x;
    uint32_t* lp = &lo.x;
#pragma unroll
    for (int p = 0; p < 4; p++) {
        __half2 a = __floats2half2_rn(f[2*p], f[2*p+1]);
        hp[p] = h2u(a);
        __half2 bq = __floats2half2_rn(f[2*p]   - __half2float(__low2half(a)),
                                       f[2*p+1] - __half2float(__high2half(a)));
        lp[p] = h2u(bq);
    }
    *reinterpret_cast<uint4*>(&g_wh[n * 64 + ch * 8]) = hi;
    *reinterpret_cast<uint4*>(&g_wl[n * 64 + ch * 8]) = lo;
}

// ---------------- Kernel 1: tensor-core QKV projection ----------------
#define XA_H 0
#define XA_L 8192
#define WW_H 16384
#define WW_L 40960
#define PROJ_SMEM 65536

extern __shared__ char psm[];

__global__ __launch_bounds__(256, 2) void proj_kernel(const float* __restrict__ x)
{
    const int tid = threadIdx.x;
    const int wid = tid >> 5, lane = tid & 31;
    const int g = lane >> 2, tq = lane & 3;
    const int rows_base = blockIdx.x * 64;
    const uint32_t smb = smem_u32(psm);

    // ---- W tiles via cp.async (coalesced, L2-resident) ----
#pragma unroll
    for (int it = 0; it < 6; it++) {
        const int id = tid + it * 256;            // 0..1535
        const int n = id >> 3, ch = id & 7;
        const uint32_t off = n * 128 + ((ch ^ (n & 7)) << 4);
        CP_ASYNC16(smb + WW_H + off, g_wh + n * 64 + ch * 8);
        CP_ASYNC16(smb + WW_L + off, g_wl + n * 64 + ch * 8);
    }
    CP_COMMIT();

    // ---- x tile: fp32 -> fp16 hi/lo (through regs) ----
#pragma unroll
    for (int it = 0; it < 2; it++) {
        const int id = tid + it * 256;            // 0..511
        const int r = id >> 3, ch = id & 7;
        const float4* xp = reinterpret_cast<const float4*>(
            x + ((size_t)(rows_base + r)) * 64 + ch * 8);
        const float4 f0 = xp[0], f1 = xp[1];
        uint4 hi, lo;
        __half2 a, bq;
        a = __floats2half2_rn(f0.x, f0.y); hi.x = h2u(a);
        bq = __floats2half2_rn(f0.x - __half2float(__low2half(a)), f0.y - __half2float(__high2half(a))); lo.x = h2u(bq);
        a = __floats2half2_rn(f0.z, f0.w); hi.y = h2u(a);
        bq = __floats2half2_rn(f0.z - __half2float(__low2half(a)), f0.w - __half2float(__high2half(a))); lo.y = h2u(bq);
        a = __floats2half2_rn(f1.x, f1.y); hi.z = h2u(a);
        bq = __floats2half2_rn(f1.x - __half2float(__low2half(a)), f1.y - __half2float(__high2half(a))); lo.z = h2u(bq);
        a = __floats2half2_rn(f1.z, f1.w); hi.w = h2u(a);
        bq = __floats2half2_rn(f1.z - __half2float(__low2half(a)), f1.w - __half2float(__high2half(a))); lo.w = h2u(bq);
        const uint32_t off = r * 128 + ((ch ^ (r & 7)) << 4);
        *reinterpret_cast<uint4*>(psm + XA_H + off) = hi;
        *reinterpret_cast<uint4*>(psm + XA_L + off) = lo;
    }
    CP_WAIT(0);
    __syncthreads();

    const uint32_t* sAh = (const uint32_t*)(psm + XA_H);
    const uint32_t* sAl = (const uint32_t*)(psm + XA_L);
    const uint32_t* sWh = (const uint32_t*)(psm + WW_H);
    const uint32_t* sWl = (const uint32_t*)(psm + WW_L);

    uint32_t ah[16], al[16];
    {
        const int rb  = ((wid & 3) * 16 + g) * 32 + tq;
        const int rb8 = rb + 256;
#pragma unroll
        for (int kc = 0; kc < 4; kc++) {
            const int e0 = ((2 * kc) ^ g) << 2;
            const int e1 = ((2 * kc + 1) ^ g) << 2;
            ah[4*kc+0] = sAh[rb + e0];  ah[4*kc+1] = sAh[rb8 + e0];
            ah[4*kc+2] = sAh[rb + e1];  ah[4*kc+3] = sAh[rb8 + e1];
            al[4*kc+0] = sAl[rb + e0];  al[4*kc+1] = sAl[rb8 + e0];
            al[4*kc+2] = sAl[rb + e1];  al[4*kc+3] = sAl[rb8 + e1];
        }
    }

    const int nh = wid >> 2;                      // n-half: 0 or 1
    float D[12][4];
#pragma unroll
    for (int j = 0; j < 12; j++) { D[j][0]=0.f; D[j][1]=0.f; D[j][2]=0.f; D[j][3]=0.f; }

#pragma unroll
    for (int jj = 0; jj < 12; jj++) {
        const int jg = nh * 12 + jj;
        const int rbase = (8 * jg + g) * 32 + tq;
#pragma unroll
        for (int kc = 0; kc < 4; kc++) {
            const int e0 = ((2 * kc) ^ g) << 2;
            const int e1 = ((2 * kc + 1) ^ g) << 2;
            const uint32_t bh0 = sWh[rbase + e0], bh1 = sWh[rbase + e1];
            const uint32_t bl0 = sWl[rbase + e0], bl1 = sWl[rbase + e1];
            MMA16816(D[jj][0],D[jj][1],D[jj][2],D[jj][3], ah[4*kc],ah[4*kc+1],ah[4*kc+2],ah[4*kc+3], bh0,bh1);
            MMA16816(D[jj][0],D[jj][1],D[jj][2],D[jj][3], al[4*kc],al[4*kc+1],al[4*kc+2],al[4*kc+3], bh0,bh1);
            MMA16816(D[jj][0],D[jj][1],D[jj][2],D[jj][3], ah[4*kc],ah[4*kc+1],ah[4*kc+2],ah[4*kc+3], bl0,bl1);
        }
    }

    // ---- epilogue ----
    const int rg  = rows_base + (wid & 3) * 16 + g;
    const int rg8 = rg + 8;
    const int b = rg >> 12, t0 = rg & (T_ - 1), t8 = t0 + 8;

#pragma unroll
    for (int jj = 0; jj < 12; jj++) {
        const int j = nh * 12 + jj;
        const int h = 8 * (j & 7) + 2 * tq;
        float v0 = D[jj][0], v1 = D[jj][1], v2 = D[jj][2], v3 = D[jj][3];
        if (j < 8) { v0 *= QSCALE; v1 *= QSCALE; v2 *= QSCALE; v3 *= QSCALE; }  // Q * C**0.5 * log2(e)
        const __half2 hA = __floats2half2_rn(v0, v1);
        const __half2 hB = __floats2half2_rn(v2, v3);
        const __half2 lA = __floats2half2_rn(v0 - __half2float(__low2half(hA)),
                                             v1 - __half2float(__high2half(hA)));
        const __half2 lB = __floats2half2_rn(v2 - __half2float(__low2half(hB)),
                                             v3 - __half2float(__high2half(hB)));
        if (j < 8) {
            *(uint32_t*)&g_qh[(size_t)rg  * 64 + h] = h2u(hA);
            *(uint32_t*)&g_qh[(size_t)rg8 * 64 + h] = h2u(hB);
            *(uint32_t*)&g_ql[(size_t)rg  * 64 + h] = h2u(lA);
            *(uint32_t*)&g_ql[(size_t)rg8 * 64 + h] = h2u(lB);
        } else if (j < 16) {
            *(uint32_t*)&g_kh[(size_t)rg  * 64 + h] = h2u(hA);
            *(uint32_t*)&g_kh[(size_t)rg8 * 64 + h] = h2u(hB);
            *(uint32_t*)&g_kl[(size_t)rg  * 64 + h] = h2u(lA);
            *(uint32_t*)&g_kl[(size_t)rg8 * 64 + h] = h2u(lB);
        } else {
            const size_t r0 = ((size_t)b * 64 + h) * T_;
            const size_t r1 = ((size_t)b * 64 + h + 1) * T_;
            g_vh[r0 + t0] = __low2half(hA);  g_vh[r1 + t0] = __high2half(hA);
            g_vh[r0 + t8] = __low2half(hB);  g_vh[r1 + t8] = __high2half(hB);
        }
    }
}

// ---------------- Kernel 2: FA2-style mma.sync flash attention (split-K partials)
// SMEM: 2 x 24KB K/V double buffer (Kh,Kl,Vh) + 32KB Q (hi/lo) = 80KB/CTA, 2 CTAs/SM.
#define ABYTES 8192
#define BUFBYTES (3 * ABYTES)
#define QH_OFF 49152
#define QL_OFF 65536
#define SMEM_BYTES 81920

extern __shared__ char dsm[];

__device__ __forceinline__ void copy_tile(int b, int k0, int buf, int tid, uint32_t smb)
{
#pragma unroll
    for (int i = 0; i < 6; i++) {
        const int id = tid + i * 256;           // 0..1535
        const int arr = id >> 9;                // 0=Kh 1=Kl 2=Vh (uniform per i-range)
        const int r = (id >> 3) & 63;
        const int ch = id & 7;
        const uint32_t dst = smb + buf * BUFBYTES + arr * ABYTES + r * 128 + ((ch ^ (r & 7)) << 4);
        const __half* src;
        if (arr == 0)      src = g_kh + ((size_t)(b * T_ + k0 + r)) * 64 + ch * 8;
        else if (arr == 1) src = g_kl + ((size_t)(b * T_ + k0 + r)) * 64 + ch * 8;
        else               src = g_vh + ((size_t)(b * 64 + r)) * T_ + k0 + ch * 8;
        CP_ASYNC16(dst, src);
    }
}

__device__ __forceinline__ void copy_q(int b, int q0, int tid, uint32_t smb)
{
#pragma unroll
    for (int i = 0; i < 8; i++) {
        const int id = tid + i * 256;           // 0..2047
        const int arr = id >> 10;               // 0=qh, 1=ql
        const int r = (id >> 3) & 127;
        const int ch = id & 7;
        const uint32_t dst = smb + QH_OFF + arr * 16384 + r * 128 + ((ch ^ (r & 7)) << 4);
        const __half* src = (arr == 0 ? g_qh : g_ql) + ((size_t)(b * T_ + q0 + r)) * 64 + ch * 8;
        CP_ASYNC16(dst, src);
    }
}

__global__ __launch_bounds__(256, 2) void attn_kernel(float* __restrict__ out)
{
    const int b = blockIdx.y;
    // heavy-first (t, c) mapping: q-tile t has t/8+1 chunks; sum = 80
    int u = blockIdx.x, t = 0, c = 0;
#pragma unroll 1
    for (int tt = 31; tt >= 0; tt--) { int n = tt / 8 + 1; if (u < n) { t = tt; c = u; break; } u -= n; }
    const int q0 = t * BM, k0c = c * KC;
    const int kend = min(k0c + KC, (t + 1) * BM);
    const int nT = (kend - k0c) / KN;
    const bool single_chunk = (t < 8);            // nc == 1: write output directly

    const int tid = threadIdx.x, wid = tid >> 5, lane = tid & 31;
    const int g = lane >> 2, tq = lane & 3;
    const int qi0 = q0 + wid * 16;
    const int rg = qi0 + g, rg8 = rg + 8;
    const uint32_t smb = smem_u32(dsm);

    // ldmatrix lane decomposition
    const int lr = lane & 7, q2 = lane >> 3;
    const uint32_t kv_row = (uint32_t)(((q2 >> 1) * 8 + lr) * 128);   // K/V: m-pair row offset
    const int eKV = q2 & 1;                                           // K/V: which k-chunk
    const uint32_t q_row = (uint32_t)((wid * 16 + (q2 & 1) * 8 + lr) * 128);  // Q rows
    const int eQ = q2 >> 1;

    float O[8][4];
#pragma unroll
    for (int j = 0; j < 8; j++) { O[j][0]=0.f; O[j][1]=0.f; O[j][2]=0.f; O[j][3]=0.f; }
    float Ol[4] = {0.f, 0.f, 0.f, 0.f};          // ones-column accumulator: l
    float m0 = -1e30f, m1 = -1e30f;

    copy_q(b, q0, tid, smb);
    copy_tile(b, k0c, 0, tid, smb);
    CP_COMMIT();
    CP_WAIT(0);
    __syncthreads();

    // ---- hoist Q-hi fragments (tile-invariant) into registers ----
    uint32_t qfh[16];
#pragma unroll
    for (int kc = 0; kc < 4; kc++) {
        const uint32_t chQ = (uint32_t)(((2 * kc + eQ) ^ lr) << 4);
        LDSM4(qfh[4*kc], qfh[4*kc+1], qfh[4*kc+2], qfh[4*kc+3], smb + QH_OFF + q_row + chQ);
    }

    for (int n = 0; n < nT; n++) {
        const int k0 = k0c + n * KN;
        const int buf = n & 1;
        // invariant at loop top: tile n resident + visible; all warps done with tile n-1
        if (n + 1 < nT) { copy_tile(b, k0 + KN, (n + 1) & 1, tid, smb); CP_COMMIT(); }

        const uint32_t kh_base = smb + buf * BUFBYTES + kv_row;
        const uint32_t vh_base = kh_base + 2 * ABYTES;

        // ---- S = Q·K^T (3-term hi/lo), Q-hi from regs; scores in log2 units ----
        float SD[8][4];
#pragma unroll
        for (int j = 0; j < 8; j++) { SD[j][0]=0.f; SD[j][1]=0.f; SD[j][2]=0.f; SD[j][3]=0.f; }
#pragma unroll
        for (int kc = 0; kc < 4; kc++) {
            const uint32_t chQ = (uint32_t)(((2 * kc + eQ) ^ lr) << 4);
            uint32_t c0r, c1r, c2r, c3r;
            LDSM4(c0r, c1r, c2r, c3r, smb + QL_OFF + q_row + chQ);
            const uint32_t a0 = qfh[4*kc], a1 = qfh[4*kc+1], a2 = qfh[4*kc+2], a3 = qfh[4*kc+3];
            const uint32_t chK = (uint32_t)(((2 * kc + eKV) ^ lr) << 4);
#pragma unroll
            for (int j0 = 0; j0 < 8; j0 += 2) {
                uint32_t bh0, bh1, bh2, bh3, bl0, bl1, bl2, bl3;
                LDSM4(bh0, bh1, bh2, bh3, kh_base + chK + j0 * 1024);
                LDSM4(bl0, bl1, bl2, bl3, kh_base + ABYTES + chK + j0 * 1024);
                MMA16816(SD[j0][0],SD[j0][1],SD[j0][2],SD[j0][3], a0,a1,a2,a3, bh0,bh1);
                MMA16816(SD[j0][0],SD[j0][1],SD[j0][2],SD[j0][3], c0r,c1r,c2r,c3r, bh0,bh1);
                MMA16816(SD[j0][0],SD[j0][1],SD[j0][2],SD[j0][3], a0,a1,a2,a3, bl0,bl1);
                MMA16816(SD[j0+1][0],SD[j0+1][1],SD[j0+1][2],SD[j0+1][3], a0,a1,a2,a3, bh2,bh3);
                MMA16816(SD[j0+1][0],SD[j0+1][1],SD[j0+1][2],SD[j0+1][3], c0r,c1r,c2r,c3r, bh2,bh3);
                MMA16816(SD[j0+1][0],SD[j0+1][1],SD[j0+1][2],SD[j0+1][3], a0,a1,a2,a3, bl2,bl3);
            }
        }

        // ---- causal mask (warp-uniform predicate) ----
        if (k0 + KN - 1 > qi0) {
#pragma unroll
            for (int j = 0; j < 8; j++) {
                const int col = k0 + 8 * j + 2 * tq;
                if (col     > rg)  SD[j][0] = -1e30f;
                if (col + 1 > rg)  SD[j][1] = -1e30f;
                if (col     > rg8) SD[j][2] = -1e30f;
                if (col + 1 > rg8) SD[j][3] = -1e30f;
            }
        }

        // ---- online softmax (log2 domain) ----
        float bm0 = -1e30f, bm1 = -1e30f;
#pragma unroll
        for (int j = 0; j < 8; j++) {
            bm0 = fmaxf(bm0, fmaxf(SD[j][0], SD[j][1]));
            bm1 = fmaxf(bm1, fmaxf(SD[j][2], SD[j][3]));
        }
        bm0 = fmaxf(bm0, __shfl_xor_sync(0xFFFFFFFFu, bm0, 1));
        bm0 = fmaxf(bm0, __shfl_xor_sync(0xFFFFFFFFu, bm0, 2));
        bm1 = fmaxf(bm1, __shfl_xor_sync(0xFFFFFFFFu, bm1, 1));
        bm1 = fmaxf(bm1, __shfl_xor_sync(0xFFFFFFFFu, bm1, 2));
        const float mn0 = fmaxf(m0, bm0), mn1 = fmaxf(m1, bm1);

        // warp-vote: skip rescale entirely when no row's max moved
        if (__any_sync(0xFFFFFFFFu, (bm0 > m0) | (bm1 > m1))) {
            const float c0 = ex2f(m0 - mn0), c1 = ex2f(m1 - mn1);
#pragma unroll
            for (int j = 0; j < 8; j++) {
                O[j][0] *= c0; O[j][1] *= c0; O[j][2] *= c1; O[j][3] *= c1;
            }
            Ol[0] *= c0; Ol[1] *= c0; Ol[2] *= c1; Ol[3] *= c1;
            m0 = mn0; m1 = mn1;
        }

        // ---- O += P·V  (p = ex2.f16x2(s - m); l via ones-column MMA; V hi only) ----
#pragma unroll
        for (int kc = 0; kc < 4; kc++) {
            const uint32_t pa0 = ex2h2(h2u(__floats2half2_rn(SD[2*kc][0]   - m0, SD[2*kc][1]   - m0)));
            const uint32_t pa1 = ex2h2(h2u(__floats2half2_rn(SD[2*kc][2]   - m1, SD[2*kc][3]   - m1)));
            const uint32_t pa2 = ex2h2(h2u(__floats2half2_rn(SD[2*kc+1][0] - m0, SD[2*kc+1][1] - m0)));
            const uint32_t pa3 = ex2h2(h2u(__floats2half2_rn(SD[2*kc+1][2] - m1, SD[2*kc+1][3] - m1)));
            MMA16816(Ol[0],Ol[1],Ol[2],Ol[3], pa0,pa1,pa2,pa3, ONES16,ONES16);
            const uint32_t chV = (uint32_t)(((2 * kc + eKV) ^ lr) << 4);
#pragma unroll
            for (int j0 = 0; j0 < 8; j0 += 2) {
                uint32_t vh0, vh1, vh2, vh3;
                LDSM4(vh0, vh1, vh2, vh3, vh_base + chV + j0 * 1024);
                MMA16816(O[j0][0],O[j0][1],O[j0][2],O[j0][3], pa0,pa1,pa2,pa3, vh0,vh1);
                MMA16816(O[j0+1][0],O[j0+1][1],O[j0+1][2],O[j0+1][3], pa0,pa1,pa2,pa3, vh2,vh3);
            }
        }

        // single barrier per tile: tile n+1 arrival + all-warps-done-tile-n
        if (n + 1 < nT) { CP_WAIT(0); }
        __syncthreads();
    }

    if (single_chunk) {
        // ---- direct output (fp32), no partials, reduce skips these rows ----
        const float inv0 = 1.0f / Ol[0], inv1 = 1.0f / Ol[2];
        float* o0 = out + ((size_t)(b * T_ + rg)) * HS_;
        float* o1 = out + ((size_t)(b * T_ + rg8)) * HS_;
#pragma unroll
        for (int j = 0; j < 8; j++) {
            float2 a; a.x = O[j][0] * inv0; a.y = O[j][1] * inv0;
            float2 d; d.x = O[j][2] * inv1; d.y = O[j][3] * inv1;
            *(float2*)&o0[8 * j + 2 * tq] = a;
            *(float2*)&o1[8 * j + 2 * tq] = d;
        }
    } else {
        // ---- write partials (m log2; l from ones-column; O as fp16) ----
        const size_t p0 = ((size_t)(b * T_ + rg)) * NCMAX + c;
        const size_t p1 = ((size_t)(b * T_ + rg8)) * NCMAX + c;
        if (tq == 0) {
            g_pm[p0] = m0; g_pl[p0] = Ol[0];
            g_pm[p1] = m1; g_pl[p1] = Ol[2];
        }
#pragma unroll
        for (int j = 0; j < 8; j++) {
            *(uint32_t*)&g_po[p0 * 64 + 8 * j + 2 * tq] = h2u(__floats2half2_rn(O[j][0], O[j][1]));
            *(uint32_t*)&g_po[p1 * 64 + 8 * j + 2 * tq] = h2u(__floats2half2_rn(O[j][2], O[j][3]));
        }
    }
}

// ---------------- Kernel 3: merge split-K partials (thread = (row, 4-col part), fp16 loads)
__global__ __launch_bounds__(256) void attn_reduce_kernel(float* __restrict__ out)
{
    const int gid2 = blockIdx.x * 256 + threadIdx.x;   // 0 .. B*T*16
    const int row = gid2 >> 4, part = gid2 & 15;
    const int qi = row & (T_ - 1);
    const int tt = qi >> 7;
    if (tt < 8) return;                                 // single-chunk rows written directly
    const int nc = tt / 8 + 1;
    const size_t pbase = (size_t)row * NCMAX;

    float mv[NCMAX];
#pragma unroll
    for (int cc = 0; cc < NCMAX; cc++) mv[cc] = (cc < nc) ? g_pm[pbase + cc] : -1e30f;
    float m = -1e30f;
#pragma unroll
    for (int cc = 0; cc < NCMAX; cc++) m = fmaxf(m, mv[cc]);

    float l = 0.f;
    float o[4];
#pragma unroll
    for (int i = 0; i < 4; i++) o[i] = 0.f;
#pragma unroll
    for (int cc = 0; cc < NCMAX; cc++) {
        if (cc < nc) {
            const float w = ex2f(mv[cc] - m);      // log2-domain partials
            l = fmaf(g_pl[pbase + cc], w, l);
            const uint2 v = *reinterpret_cast<const uint2*>(
                &g_po[(pbase + cc) * HS_ + part * 4]);
            const float2 f0 = __half22float2(*(const __half2*)&v.x);
            const float2 f1 = __half22float2(*(const __half2*)&v.y);
            o[0] = fmaf(w, f0.x, o[0]); o[1] = fmaf(w, f0.y, o[1]);
            o[2] = fmaf(w, f1.x, o[2]); o[3] = fmaf(w, f1.y, o[3]);
        }
    }
    const float inv = 1.0f / l;
    float4 r;
    r.x = o[0]*inv; r.y = o[1]*inv; r.z = o[2]*inv; r.w = o[3]*inv;
    *reinterpret_cast<float4*>(&out[(size_t)row * HS_ + part * 4]) = r;
}

// ---------------------------------------------------------------------------
extern "C" void kernel_launch(void* const* d_in, const int* in_sizes, int n_in,
                              void* d_out, int out_size)
{
    const float* x  = (const float*)d_in[0];
    const float* Wq = (const float*)d_in[1];
    const float* Wk = (const float*)d_in[2];
    const float* Wv = (const float*)d_in[3];
    float* out = (float*)d_out;

    cudaFuncSetAttribute(proj_kernel, cudaFuncAttributeMaxDynamicSharedMemorySize, PROJ_SMEM);
    cudaFuncSetAttribute(attn_kernel, cudaFuncAttributeMaxDynamicSharedMemorySize, SMEM_BYTES);

    wconv_kernel<<<6, 256>>>(Wq, Wk, Wv);
    proj_kernel<<<(B_ * T_) / 64, 256, PROJ_SMEM>>>(x);

    dim3 ag(80, B_);
    attn_kernel<<<ag, 256, SMEM_BYTES>>>(out);

    attn_reduce_kernel<<<(B_ * T_ * 16) / 256, 256>>>(out);
}